// round 3
// baseline (speedup 1.0000x reference)
#include <cuda_runtime.h>
#include <math.h>

#define T_TOK 1024
#define DDIM  1024
#define FDIM  2048
#define NEXP  16

#define BM 128
#define BN 64
#define BK 16
#define ASTR (BK + 4)   // 20 floats, conflict-free for the mma A read pattern
#define BSTR (BN + 8)   // 72 floats, conflict-free for the mma B read pattern

// ---- device scratch (no allocations allowed) ----
__device__ __align__(16) int   g_cnt[NEXP];
__device__ __align__(16) int   g_lst[NEXP * T_TOK];     // entries: token*2 + slot
__device__ __align__(16) float g_wt[2 * T_TOK];         // renormalized top-2 weights
__device__ __align__(256) float g_h[2 * T_TOK * FDIM];  // 16 MB: silu(g)*u per assignment

// ---------------------------------------------------------------- helpers
__device__ __forceinline__ unsigned cvt_tf32(float x) {
    unsigned r;
    asm("cvt.rna.tf32.f32 %0, %1;" : "=r"(r) : "f"(x));
    return r;
}
__device__ __forceinline__ void cpa16(void* smem, const void* g) {
    unsigned s = (unsigned)__cvta_generic_to_shared(smem);
    asm volatile("cp.async.cg.shared.global [%0], [%1], 16;" :: "r"(s), "l"(g));
}
__device__ __forceinline__ void cpa_commit() { asm volatile("cp.async.commit_group;"); }
__device__ __forceinline__ void cpa_wait1() { asm volatile("cp.async.wait_group 1;"); }
__device__ __forceinline__ void cpa_wait0() { asm volatile("cp.async.wait_group 0;"); }

__device__ __forceinline__ void mma_tf32(float& c0, float& c1, float& c2, float& c3,
                                         unsigned a0, unsigned a1, unsigned a2, unsigned a3,
                                         unsigned b0, unsigned b1) {
    asm volatile(
        "mma.sync.aligned.m16n8k8.row.col.f32.tf32.tf32.f32 "
        "{%0,%1,%2,%3},{%4,%5,%6,%7},{%8,%9},{%0,%1,%2,%3};"
        : "+f"(c0), "+f"(c1), "+f"(c2), "+f"(c3)
        : "r"(a0), "r"(a1), "r"(a2), "r"(a3), "r"(b0), "r"(b1));
}

// ---------------------------------------------------------------- init
__global__ void init_kernel(float* __restrict__ out) {
    int i = blockIdx.x * blockDim.x + threadIdx.x;
    if (i < T_TOK * DDIM) out[i] = 0.0f;
    if (i < NEXP) g_cnt[i] = 0;
}

// ---------------------------------------------------------------- router (warp per token)
__global__ void router_kernel(const float* __restrict__ x, const float* __restrict__ rw) {
    int warp = (blockIdx.x * blockDim.x + threadIdx.x) >> 5;
    int lane = threadIdx.x & 31;
    if (warp >= T_TOK) return;
    const float* xr = x + (size_t)warp * DDIM;

    float acc[NEXP];
#pragma unroll
    for (int e = 0; e < NEXP; e++) acc[e] = 0.0f;

    for (int d = lane; d < DDIM; d += 32) {
        float xv = xr[d];
        const float* rwr = rw + (size_t)d * NEXP;
#pragma unroll
        for (int e = 0; e < NEXP; e++) acc[e] += xv * rwr[e];
    }
#pragma unroll
    for (int e = 0; e < NEXP; e++)
#pragma unroll
        for (int off = 16; off > 0; off >>= 1)
            acc[e] += __shfl_down_sync(0xFFFFFFFFu, acc[e], off);

    if (lane == 0) {
        int e0 = 0; float l0 = acc[0];
#pragma unroll
        for (int e = 1; e < NEXP; e++)
            if (acc[e] > l0) { l0 = acc[e]; e0 = e; }
        int e1 = -1; float l1 = -3.4e38f;
#pragma unroll
        for (int e = 0; e < NEXP; e++)
            if (e != e0 && acc[e] > l1) { l1 = acc[e]; e1 = e; }
        // softmax normalizer cancels in the top-2 renormalization
        float t  = expf(l1 - l0);
        float w0 = 1.0f / (1.0f + t);
        float w1 = t / (1.0f + t);
        g_wt[2 * warp + 0] = w0;
        g_wt[2 * warp + 1] = w1;
        int p0 = atomicAdd(&g_cnt[e0], 1);
        g_lst[e0 * T_TOK + p0] = warp * 2 + 0;
        int p1 = atomicAdd(&g_cnt[e1], 1);
        g_lst[e1 * T_TOK + p1] = warp * 2 + 1;
    }
}

// ---------------------------------------------------------------- GEMM1: h = silu(X@Wg)*(X@Wu)
__global__ __launch_bounds__(256, 1) void gemm1_kernel(
    const float* __restrict__ x, const float* __restrict__ wg, const float* __restrict__ wu) {
    int e = blockIdx.z, mt = blockIdx.y, ft = blockIdx.x;
    int cnt = g_cnt[e];
    if (mt * BM >= cnt) return;

    __shared__ __align__(16) float sA[2][BM][ASTR];
    __shared__ __align__(16) float sG[2][BK][BSTR];
    __shared__ __align__(16) float sU[2][BK][BSTR];
    __shared__ int sIdx[BM];

    int tid = threadIdx.x;
    if (tid < BM) {
        int gi = mt * BM + tid;
        sIdx[tid] = g_lst[e * T_TOK + (gi < cnt ? gi : cnt - 1)];
    }
    __syncthreads();

    const float* wgE = wg + (size_t)e * DDIM * FDIM + ft * BN;
    const float* wuE = wu + (size_t)e * DDIM * FDIM + ft * BN;

    int aRow = tid >> 2, aSeg = tid & 3;     // A: 64 rows x 4 segs per half
    int bRow = tid >> 4, bSeg = tid & 15;    // B: 16 rows x 16 segs
    const float* aP0 = x + (size_t)(sIdx[aRow] >> 1) * DDIM + aSeg * 4;
    const float* aP1 = x + (size_t)(sIdx[aRow + 64] >> 1) * DDIM + aSeg * 4;

    int lane = tid & 31, warp = tid >> 5;
    int wm = (warp & 3) * 32, wn = (warp >> 2) * 32;
    int qr = lane >> 2, qc = lane & 3;

    float cg[2][4][4], cu[2][4][4];
#pragma unroll
    for (int i = 0; i < 2; i++)
#pragma unroll
        for (int j = 0; j < 4; j++)
#pragma unroll
            for (int k = 0; k < 4; k++) { cg[i][j][k] = 0.f; cu[i][j][k] = 0.f; }

    auto prefetch = [&](int k0, int buf) {
        cpa16(&sA[buf][aRow][aSeg * 4],      aP0 + k0);
        cpa16(&sA[buf][aRow + 64][aSeg * 4], aP1 + k0);
        cpa16(&sG[buf][bRow][bSeg * 4], wgE + (size_t)(k0 + bRow) * FDIM + bSeg * 4);
        cpa16(&sU[buf][bRow][bSeg * 4], wuE + (size_t)(k0 + bRow) * FDIM + bSeg * 4);
        cpa_commit();
    };

    prefetch(0, 0);
    const int KT = DDIM / BK;  // 64
    for (int kt = 0; kt < KT; kt++) {
        if (kt + 1 < KT) { prefetch((kt + 1) * BK, (kt + 1) & 1); cpa_wait1(); }
        else             { cpa_wait0(); }
        __syncthreads();
        int buf = kt & 1;
#pragma unroll
        for (int ks = 0; ks < 2; ks++) {
            int k = ks * 8;
            unsigned af[2][4];
#pragma unroll
            for (int mf = 0; mf < 2; mf++) {
                int r = wm + mf * 16 + qr;
                af[mf][0] = cvt_tf32(sA[buf][r    ][k + qc]);
                af[mf][1] = cvt_tf32(sA[buf][r + 8][k + qc]);
                af[mf][2] = cvt_tf32(sA[buf][r    ][k + qc + 4]);
                af[mf][3] = cvt_tf32(sA[buf][r + 8][k + qc + 4]);
            }
#pragma unroll
            for (int nf = 0; nf < 4; nf++) {
                int c = wn + nf * 8 + qr;
                unsigned bg0 = cvt_tf32(sG[buf][k + qc    ][c]);
                unsigned bg1 = cvt_tf32(sG[buf][k + qc + 4][c]);
                unsigned bu0 = cvt_tf32(sU[buf][k + qc    ][c]);
                unsigned bu1 = cvt_tf32(sU[buf][k + qc + 4][c]);
#pragma unroll
                for (int mf = 0; mf < 2; mf++) {
                    mma_tf32(cg[mf][nf][0], cg[mf][nf][1], cg[mf][nf][2], cg[mf][nf][3],
                             af[mf][0], af[mf][1], af[mf][2], af[mf][3], bg0, bg1);
                    mma_tf32(cu[mf][nf][0], cu[mf][nf][1], cu[mf][nf][2], cu[mf][nf][3],
                             af[mf][0], af[mf][1], af[mf][2], af[mf][3], bu0, bu1);
                }
            }
        }
        __syncthreads();
    }

    // epilogue: h = silu(g)*u, float2 stores (full 32B sectors)
#pragma unroll
    for (int mf = 0; mf < 2; mf++)
#pragma unroll
        for (int half = 0; half < 2; half++) {
            int rl = wm + mf * 16 + qr + half * 8;
            int gi = mt * BM + rl;
            if (gi < cnt) {
                int a = sIdx[rl];
                float* hp = g_h + (size_t)a * FDIM + ft * BN;
#pragma unroll
                for (int nf = 0; nf < 4; nf++) {
                    float gv0 = cg[mf][nf][half * 2 + 0], gv1 = cg[mf][nf][half * 2 + 1];
                    float uv0 = cu[mf][nf][half * 2 + 0], uv1 = cu[mf][nf][half * 2 + 1];
                    float h0 = gv0 / (1.0f + __expf(-gv0)) * uv0;
                    float h1 = gv1 / (1.0f + __expf(-gv1)) * uv1;
                    int c = wn + nf * 8 + qc * 2;
                    *reinterpret_cast<float2*>(hp + c) = make_float2(h0, h1);
                }
            }
        }
}

// ---------------------------------------------------------------- GEMM2: out += w * (h @ Wd)
__global__ __launch_bounds__(256, 1) void gemm2_kernel(
    const float* __restrict__ wd, float* __restrict__ out) {
    int e = blockIdx.z, mt = blockIdx.y, nt = blockIdx.x;
    int cnt = g_cnt[e];
    if (mt * BM >= cnt) return;

    __shared__ __align__(16) float sA[2][BM][ASTR];
    __shared__ __align__(16) float sB[2][BK][BSTR];
    __shared__ int   sIdx[BM];
    __shared__ float sW[BM];

    int tid = threadIdx.x;
    if (tid < BM) {
        int gi = mt * BM + tid;
        int a = g_lst[e * T_TOK + (gi < cnt ? gi : cnt - 1)];
        sIdx[tid] = a;
        sW[tid] = g_wt[a];
    }
    __syncthreads();

    const float* wdE = wd + (size_t)e * FDIM * DDIM + nt * BN;

    int aRow = tid >> 2, aSeg = tid & 3;
    int bRow = tid >> 4, bSeg = tid & 15;
    const float* aP0 = g_h + (size_t)sIdx[aRow] * FDIM + aSeg * 4;
    const float* aP1 = g_h + (size_t)sIdx[aRow + 64] * FDIM + aSeg * 4;

    int lane = tid & 31, warp = tid >> 5;
    int wm = (warp & 3) * 32, wn = (warp >> 2) * 32;
    int qr = lane >> 2, qc = lane & 3;

    float cc[2][4][4];
#pragma unroll
    for (int i = 0; i < 2; i++)
#pragma unroll
        for (int j = 0; j < 4; j++)
#pragma unroll
            for (int k = 0; k < 4; k++) cc[i][j][k] = 0.f;

    auto prefetch = [&](int k0, int buf) {
        cpa16(&sA[buf][aRow][aSeg * 4],      aP0 + k0);
        cpa16(&sA[buf][aRow + 64][aSeg * 4], aP1 + k0);
        cpa16(&sB[buf][bRow][bSeg * 4], wdE + (size_t)(k0 + bRow) * DDIM + bSeg * 4);
        cpa_commit();
    };

    prefetch(0, 0);
    const int KT = FDIM / BK;  // 128
    for (int kt = 0; kt < KT; kt++) {
        if (kt + 1 < KT) { prefetch((kt + 1) * BK, (kt + 1) & 1); cpa_wait1(); }
        else             { cpa_wait0(); }
        __syncthreads();
        int buf = kt & 1;
#pragma unroll
        for (int ks = 0; ks < 2; ks++) {
            int k = ks * 8;
            unsigned af[2][4];
#pragma unroll
            for (int mf = 0; mf < 2; mf++) {
                int r = wm + mf * 16 + qr;
                af[mf][0] = cvt_tf32(sA[buf][r    ][k + qc]);
                af[mf][1] = cvt_tf32(sA[buf][r + 8][k + qc]);
                af[mf][2] = cvt_tf32(sA[buf][r    ][k + qc + 4]);
                af[mf][3] = cvt_tf32(sA[buf][r + 8][k + qc + 4]);
            }
#pragma unroll
            for (int nf = 0; nf < 4; nf++) {
                int c = wn + nf * 8 + qr;
                unsigned b0 = cvt_tf32(sB[buf][k + qc    ][c]);
                unsigned b1 = cvt_tf32(sB[buf][k + qc + 4][c]);
#pragma unroll
                for (int mf = 0; mf < 2; mf++)
                    mma_tf32(cc[mf][nf][0], cc[mf][nf][1], cc[mf][nf][2], cc[mf][nf][3],
                             af[mf][0], af[mf][1], af[mf][2], af[mf][3], b0, b1);
            }
        }
        __syncthreads();
    }

    // epilogue: weighted atomic scatter (exactly 2 adds per out element -> deterministic)
#pragma unroll
    for (int mf = 0; mf < 2; mf++)
#pragma unroll
        for (int half = 0; half < 2; half++) {
            int rl = wm + mf * 16 + qr + half * 8;
            int gi = mt * BM + rl;
            if (gi < cnt) {
                int a = sIdx[rl];
                int tok = a >> 1;
                float w = sW[rl];
                float* op = out + (size_t)tok * DDIM + nt * BN;
#pragma unroll
                for (int nf = 0; nf < 4; nf++) {
                    int c = wn + nf * 8 + qc * 2;
                    atomicAdd(op + c,     cc[mf][nf][half * 2 + 0] * w);
                    atomicAdd(op + c + 1, cc[mf][nf][half * 2 + 1] * w);
                }
            }
        }
}

// ---------------------------------------------------------------- launch
extern "C" void kernel_launch(void* const* d_in, const int* in_sizes, int n_in,
                              void* d_out, int out_size) {
    const float* x  = (const float*)d_in[0];
    const float* rw = (const float*)d_in[1];
    const float* wg = (const float*)d_in[2];
    const float* wu = (const float*)d_in[3];
    const float* wd = (const float*)d_in[4];
    float* out = (float*)d_out;

    init_kernel<<<(T_TOK * DDIM + 255) / 256, 256>>>(out);
    router_kernel<<<(T_TOK * 32 + 255) / 256, 256>>>(x, rw);

    dim3 g1(FDIM / BN, T_TOK / BM, NEXP);  // (32, 8, 16)
    gemm1_kernel<<<g1, 256>>>(x, wg, wu);

    dim3 g2(DDIM / BN, T_TOK / BM, NEXP);  // (16, 8, 16)
    gemm2_kernel<<<g2, 256>>>(wd, out);
}

// round 4
// speedup vs baseline: 1.0101x; 1.0101x over previous
#include <cuda_runtime.h>
#include <math.h>

#define T_TOK 1024
#define DDIM  1024
#define FDIM  2048
#define NEXP  16

#define BM 128
#define BN 64
#define BK 16
#define ASTR (BK + 4)   // 20 floats, conflict-free for the mma A read pattern
#define BSTR (BN + 8)   // 72 floats, conflict-free for the mma B read pattern

// ---- device scratch (no allocations allowed) ----
__device__ __align__(16) int   g_cnt[NEXP];
__device__ __align__(16) int   g_lst[NEXP * T_TOK];     // entries: token*2 + slot
__device__ __align__(16) float g_wt[2 * T_TOK];         // renormalized top-2 weights
__device__ __align__(256) float g_h[2 * T_TOK * FDIM];  // 16 MB: silu(g)*u per assignment

// ---------------------------------------------------------------- helpers
__device__ __forceinline__ unsigned cvt_tf32(float x) {
    unsigned r;
    asm("cvt.rna.tf32.f32 %0, %1;" : "=r"(r) : "f"(x));
    return r;
}
__device__ __forceinline__ void cpa16(void* smem, const void* g) {
    unsigned s = (unsigned)__cvta_generic_to_shared(smem);
    asm volatile("cp.async.cg.shared.global [%0], [%1], 16;" :: "r"(s), "l"(g));
}
__device__ __forceinline__ void cpa_commit() { asm volatile("cp.async.commit_group;"); }
__device__ __forceinline__ void cpa_wait1() { asm volatile("cp.async.wait_group 1;"); }
__device__ __forceinline__ void cpa_wait0() { asm volatile("cp.async.wait_group 0;"); }

__device__ __forceinline__ void mma_tf32(float& c0, float& c1, float& c2, float& c3,
                                         unsigned a0, unsigned a1, unsigned a2, unsigned a3,
                                         unsigned b0, unsigned b1) {
    asm volatile(
        "mma.sync.aligned.m16n8k8.row.col.f32.tf32.tf32.f32 "
        "{%0,%1,%2,%3},{%4,%5,%6,%7},{%8,%9},{%0,%1,%2,%3};"
        : "+f"(c0), "+f"(c1), "+f"(c2), "+f"(c3)
        : "r"(a0), "r"(a1), "r"(a2), "r"(a3), "r"(b0), "r"(b1));
}

// ---------------------------------------------------------------- init
__global__ void init_kernel(float* __restrict__ out) {
    int i = blockIdx.x * blockDim.x + threadIdx.x;
    if (i < T_TOK * DDIM) out[i] = 0.0f;
    if (i < NEXP) g_cnt[i] = 0;
}

// ---------------------------------------------------------------- router (warp per token)
__global__ void router_kernel(const float* __restrict__ x, const float* __restrict__ rw) {
    int warp = (blockIdx.x * blockDim.x + threadIdx.x) >> 5;
    int lane = threadIdx.x & 31;
    if (warp >= T_TOK) return;
    const float* xr = x + (size_t)warp * DDIM;

    float acc[NEXP];
#pragma unroll
    for (int e = 0; e < NEXP; e++) acc[e] = 0.0f;

    for (int d = lane; d < DDIM; d += 32) {
        float xv = xr[d];
        const float* rwr = rw + (size_t)d * NEXP;
#pragma unroll
        for (int e = 0; e < NEXP; e++) acc[e] += xv * rwr[e];
    }
#pragma unroll
    for (int e = 0; e < NEXP; e++)
#pragma unroll
        for (int off = 16; off > 0; off >>= 1)
            acc[e] += __shfl_down_sync(0xFFFFFFFFu, acc[e], off);

    if (lane == 0) {
        int e0 = 0; float l0 = acc[0];
#pragma unroll
        for (int e = 1; e < NEXP; e++)
            if (acc[e] > l0) { l0 = acc[e]; e0 = e; }
        int e1 = -1; float l1 = -3.4e38f;
#pragma unroll
        for (int e = 0; e < NEXP; e++)
            if (e != e0 && acc[e] > l1) { l1 = acc[e]; e1 = e; }
        // softmax normalizer cancels in the top-2 renormalization
        float t  = expf(l1 - l0);
        float w0 = 1.0f / (1.0f + t);
        float w1 = t / (1.0f + t);
        g_wt[2 * warp + 0] = w0;
        g_wt[2 * warp + 1] = w1;
        int p0 = atomicAdd(&g_cnt[e0], 1);
        g_lst[e0 * T_TOK + p0] = warp * 2 + 0;
        int p1 = atomicAdd(&g_cnt[e1], 1);
        g_lst[e1 * T_TOK + p1] = warp * 2 + 1;
    }
}

// ---------------------------------------------------------------- GEMM1: h = silu(X@Wg)*(X@Wu)
__global__ __launch_bounds__(256, 1) void gemm1_kernel(
    const float* __restrict__ x, const float* __restrict__ wg, const float* __restrict__ wu) {
    int e = blockIdx.z, mt = blockIdx.y, ft = blockIdx.x;
    int cnt = g_cnt[e];
    if (mt * BM >= cnt) return;

    __shared__ __align__(16) float sA[2][BM][ASTR];
    __shared__ __align__(16) float sG[2][BK][BSTR];
    __shared__ __align__(16) float sU[2][BK][BSTR];
    __shared__ int sIdx[BM];

    int tid = threadIdx.x;
    if (tid < BM) {
        int gi = mt * BM + tid;
        sIdx[tid] = g_lst[e * T_TOK + (gi < cnt ? gi : cnt - 1)];
    }
    __syncthreads();

    const float* wgE = wg + (size_t)e * DDIM * FDIM + ft * BN;
    const float* wuE = wu + (size_t)e * DDIM * FDIM + ft * BN;

    int aRow = tid >> 2, aSeg = tid & 3;     // A: 64 rows x 4 segs per half
    int bRow = tid >> 4, bSeg = tid & 15;    // B: 16 rows x 16 segs
    const float* aP0 = x + (size_t)(sIdx[aRow] >> 1) * DDIM + aSeg * 4;
    const float* aP1 = x + (size_t)(sIdx[aRow + 64] >> 1) * DDIM + aSeg * 4;

    int lane = tid & 31, warp = tid >> 5;
    int wm = (warp & 3) * 32, wn = (warp >> 2) * 32;
    int qr = lane >> 2, qc = lane & 3;

    float cg[2][4][4], cu[2][4][4];
#pragma unroll
    for (int i = 0; i < 2; i++)
#pragma unroll
        for (int j = 0; j < 4; j++)
#pragma unroll
            for (int k = 0; k < 4; k++) { cg[i][j][k] = 0.f; cu[i][j][k] = 0.f; }

    auto prefetch = [&](int k0, int buf) {
        cpa16(&sA[buf][aRow][aSeg * 4],      aP0 + k0);
        cpa16(&sA[buf][aRow + 64][aSeg * 4], aP1 + k0);
        cpa16(&sG[buf][bRow][bSeg * 4], wgE + (size_t)(k0 + bRow) * FDIM + bSeg * 4);
        cpa16(&sU[buf][bRow][bSeg * 4], wuE + (size_t)(k0 + bRow) * FDIM + bSeg * 4);
        cpa_commit();
    };

    prefetch(0, 0);
    const int KT = DDIM / BK;  // 64
    for (int kt = 0; kt < KT; kt++) {
        if (kt + 1 < KT) { prefetch((kt + 1) * BK, (kt + 1) & 1); cpa_wait1(); }
        else             { cpa_wait0(); }
        __syncthreads();
        int buf = kt & 1;
#pragma unroll
        for (int ks = 0; ks < 2; ks++) {
            int k = ks * 8;
            unsigned af[2][4];
#pragma unroll
            for (int mf = 0; mf < 2; mf++) {
                int r = wm + mf * 16 + qr;
                af[mf][0] = cvt_tf32(sA[buf][r    ][k + qc]);
                af[mf][1] = cvt_tf32(sA[buf][r + 8][k + qc]);
                af[mf][2] = cvt_tf32(sA[buf][r    ][k + qc + 4]);
                af[mf][3] = cvt_tf32(sA[buf][r + 8][k + qc + 4]);
            }
#pragma unroll
            for (int nf = 0; nf < 4; nf++) {
                int c = wn + nf * 8 + qr;
                unsigned bg0 = cvt_tf32(sG[buf][k + qc    ][c]);
                unsigned bg1 = cvt_tf32(sG[buf][k + qc + 4][c]);
                unsigned bu0 = cvt_tf32(sU[buf][k + qc    ][c]);
                unsigned bu1 = cvt_tf32(sU[buf][k + qc + 4][c]);
#pragma unroll
                for (int mf = 0; mf < 2; mf++) {
                    mma_tf32(cg[mf][nf][0], cg[mf][nf][1], cg[mf][nf][2], cg[mf][nf][3],
                             af[mf][0], af[mf][1], af[mf][2], af[mf][3], bg0, bg1);
                    mma_tf32(cu[mf][nf][0], cu[mf][nf][1], cu[mf][nf][2], cu[mf][nf][3],
                             af[mf][0], af[mf][1], af[mf][2], af[mf][3], bu0, bu1);
                }
            }
        }
        __syncthreads();
    }

    // epilogue: h = silu(g)*u, float2 stores (full 32B sectors)
#pragma unroll
    for (int mf = 0; mf < 2; mf++)
#pragma unroll
        for (int half = 0; half < 2; half++) {
            int rl = wm + mf * 16 + qr + half * 8;
            int gi = mt * BM + rl;
            if (gi < cnt) {
                int a = sIdx[rl];
                float* hp = g_h + (size_t)a * FDIM + ft * BN;
#pragma unroll
                for (int nf = 0; nf < 4; nf++) {
                    float gv0 = cg[mf][nf][half * 2 + 0], gv1 = cg[mf][nf][half * 2 + 1];
                    float uv0 = cu[mf][nf][half * 2 + 0], uv1 = cu[mf][nf][half * 2 + 1];
                    float h0 = gv0 / (1.0f + __expf(-gv0)) * uv0;
                    float h1 = gv1 / (1.0f + __expf(-gv1)) * uv1;
                    int c = wn + nf * 8 + qc * 2;
                    *reinterpret_cast<float2*>(hp + c) = make_float2(h0, h1);
                }
            }
        }
}

// ---------------------------------------------------------------- GEMM2: out += w * (h @ Wd)
__global__ __launch_bounds__(256, 1) void gemm2_kernel(
    const float* __restrict__ wd, float* __restrict__ out) {
    int e = blockIdx.z, mt = blockIdx.y, nt = blockIdx.x;
    int cnt = g_cnt[e];
    if (mt * BM >= cnt) return;

    __shared__ __align__(16) float sA[2][BM][ASTR];
    __shared__ __align__(16) float sB[2][BK][BSTR];
    __shared__ int   sIdx[BM];
    __shared__ float sW[BM];

    int tid = threadIdx.x;
    if (tid < BM) {
        int gi = mt * BM + tid;
        int a = g_lst[e * T_TOK + (gi < cnt ? gi : cnt - 1)];
        sIdx[tid] = a;
        sW[tid] = g_wt[a];
    }
    __syncthreads();

    const float* wdE = wd + (size_t)e * FDIM * DDIM + nt * BN;

    int aRow = tid >> 2, aSeg = tid & 3;
    int bRow = tid >> 4, bSeg = tid & 15;
    const float* aP0 = g_h + (size_t)sIdx[aRow] * FDIM + aSeg * 4;
    const float* aP1 = g_h + (size_t)sIdx[aRow + 64] * FDIM + aSeg * 4;

    int lane = tid & 31, warp = tid >> 5;
    int wm = (warp & 3) * 32, wn = (warp >> 2) * 32;
    int qr = lane >> 2, qc = lane & 3;

    float cc[2][4][4];
#pragma unroll
    for (int i = 0; i < 2; i++)
#pragma unroll
        for (int j = 0; j < 4; j++)
#pragma unroll
            for (int k = 0; k < 4; k++) cc[i][j][k] = 0.f;

    auto prefetch = [&](int k0, int buf) {
        cpa16(&sA[buf][aRow][aSeg * 4],      aP0 + k0);
        cpa16(&sA[buf][aRow + 64][aSeg * 4], aP1 + k0);
        cpa16(&sB[buf][bRow][bSeg * 4], wdE + (size_t)(k0 + bRow) * DDIM + bSeg * 4);
        cpa_commit();
    };

    prefetch(0, 0);
    const int KT = FDIM / BK;  // 128
    for (int kt = 0; kt < KT; kt++) {
        if (kt + 1 < KT) { prefetch((kt + 1) * BK, (kt + 1) & 1); cpa_wait1(); }
        else             { cpa_wait0(); }
        __syncthreads();
        int buf = kt & 1;
#pragma unroll
        for (int ks = 0; ks < 2; ks++) {
            int k = ks * 8;
            unsigned af[2][4];
#pragma unroll
            for (int mf = 0; mf < 2; mf++) {
                int r = wm + mf * 16 + qr;
                af[mf][0] = cvt_tf32(sA[buf][r    ][k + qc]);
                af[mf][1] = cvt_tf32(sA[buf][r + 8][k + qc]);
                af[mf][2] = cvt_tf32(sA[buf][r    ][k + qc + 4]);
                af[mf][3] = cvt_tf32(sA[buf][r + 8][k + qc + 4]);
            }
#pragma unroll
            for (int nf = 0; nf < 4; nf++) {
                int c = wn + nf * 8 + qr;
                unsigned b0 = cvt_tf32(sB[buf][k + qc    ][c]);
                unsigned b1 = cvt_tf32(sB[buf][k + qc + 4][c]);
#pragma unroll
                for (int mf = 0; mf < 2; mf++)
                    mma_tf32(cc[mf][nf][0], cc[mf][nf][1], cc[mf][nf][2], cc[mf][nf][3],
                             af[mf][0], af[mf][1], af[mf][2], af[mf][3], b0, b1);
            }
        }
        __syncthreads();
    }

    // epilogue: weighted atomic scatter (exactly 2 adds per out element -> deterministic)
#pragma unroll
    for (int mf = 0; mf < 2; mf++)
#pragma unroll
        for (int half = 0; half < 2; half++) {
            int rl = wm + mf * 16 + qr + half * 8;
            int gi = mt * BM + rl;
            if (gi < cnt) {
                int a = sIdx[rl];
                int tok = a >> 1;
                float w = sW[rl];
                float* op = out + (size_t)tok * DDIM + nt * BN;
#pragma unroll
                for (int nf = 0; nf < 4; nf++) {
                    int c = wn + nf * 8 + qc * 2;
                    atomicAdd(op + c,     cc[mf][nf][half * 2 + 0] * w);
                    atomicAdd(op + c + 1, cc[mf][nf][half * 2 + 1] * w);
                }
            }
        }
}

// ---------------------------------------------------------------- launch
extern "C" void kernel_launch(void* const* d_in, const int* in_sizes, int n_in,
                              void* d_out, int out_size) {
    const float* x  = (const float*)d_in[0];
    const float* rw = (const float*)d_in[1];
    const float* wg = (const float*)d_in[2];
    const float* wu = (const float*)d_in[3];
    const float* wd = (const float*)d_in[4];
    float* out = (float*)d_out;

    init_kernel<<<(T_TOK * DDIM + 255) / 256, 256>>>(out);
    router_kernel<<<(T_TOK * 32 + 255) / 256, 256>>>(x, rw);

    dim3 g1(FDIM / BN, T_TOK / BM, NEXP);  // (32, 8, 16)
    gemm1_kernel<<<g1, 256>>>(x, wg, wu);

    dim3 g2(DDIM / BN, T_TOK / BM, NEXP);  // (16, 8, 16)
    gemm2_kernel<<<g2, 256>>>(wd, out);
}

// round 5
// speedup vs baseline: 1.2082x; 1.1961x over previous
#include <cuda_runtime.h>
#include <math.h>

#define T_TOK 1024
#define DDIM  1024
#define FDIM  2048
#define NEXP  16

#define BM 128
#define BN 64
#define BK 32
#define ASTR 36          // BK+4 floats; conflict-free A reads, 16B-aligned rows (144B)
#define BSTR 72          // BN+8 floats; conflict-free B reads, 16B-aligned rows (288B)
#define S1 3             // gemm1 pipeline stages
#define S2 4             // gemm2 pipeline stages
#define ASZ (BM * ASTR)  // 4608 floats / stage
#define BSZ (BK * BSTR)  // 2304 floats / stage

#define SMEM1 (S1 * (ASZ + 2 * BSZ) * 4)  // 110592 B
#define SMEM2 (S2 * (ASZ + BSZ) * 4)      // 110592 B

// ---- device scratch (no allocations allowed) ----
__device__ __align__(16) int   g_cnt[NEXP];
__device__ __align__(16) int   g_lst[NEXP * T_TOK];     // entries: token*2 + slot
__device__ __align__(16) float g_wt[2 * T_TOK];         // renormalized top-2 weights
__device__ __align__(256) float g_xr[T_TOK * DDIM];     // x pre-rounded to tf32 bits
__device__ __align__(256) float g_h[2 * T_TOK * FDIM];  // 16 MB: silu(g)*u (tf32-rounded)

// ---------------------------------------------------------------- helpers
__device__ __forceinline__ unsigned cvt_tf32(float x) {
    unsigned r;
    asm("cvt.rna.tf32.f32 %0, %1;" : "=r"(r) : "f"(x));
    return r;
}
__device__ __forceinline__ void cpa16(void* smem, const void* g) {
    unsigned s = (unsigned)__cvta_generic_to_shared(smem);
    asm volatile("cp.async.cg.shared.global [%0], [%1], 16;" :: "r"(s), "l"(g));
}
__device__ __forceinline__ void cpa_commit() { asm volatile("cp.async.commit_group;"); }
__device__ __forceinline__ void cpa_wait1() { asm volatile("cp.async.wait_group 1;"); }
__device__ __forceinline__ void cpa_wait2() { asm volatile("cp.async.wait_group 2;"); }

__device__ __forceinline__ void mma_tf32(float& c0, float& c1, float& c2, float& c3,
                                         unsigned a0, unsigned a1, unsigned a2, unsigned a3,
                                         unsigned b0, unsigned b1) {
    asm volatile(
        "mma.sync.aligned.m16n8k8.row.col.f32.tf32.tf32.f32 "
        "{%0,%1,%2,%3},{%4,%5,%6,%7},{%8,%9},{%0,%1,%2,%3};"
        : "+f"(c0), "+f"(c1), "+f"(c2), "+f"(c3)
        : "r"(a0), "r"(a1), "r"(a2), "r"(a3), "r"(b0), "r"(b1));
}

// ---------------------------------------------------------------- init (+ pre-round x)
__global__ void init_kernel(float* __restrict__ out, const float* __restrict__ x) {
    int i = blockIdx.x * blockDim.x + threadIdx.x;
    if (i < T_TOK * DDIM) {
        out[i] = 0.0f;
        g_xr[i] = __uint_as_float(cvt_tf32(x[i]));
    }
    if (i < NEXP) g_cnt[i] = 0;
}

// ---------------------------------------------------------------- router (warp per token)
__global__ void router_kernel(const float* __restrict__ x, const float* __restrict__ rw) {
    int warp = (blockIdx.x * blockDim.x + threadIdx.x) >> 5;
    int lane = threadIdx.x & 31;
    if (warp >= T_TOK) return;
    const float* xr = x + (size_t)warp * DDIM;

    float acc[NEXP];
#pragma unroll
    for (int e = 0; e < NEXP; e++) acc[e] = 0.0f;

    for (int d = lane; d < DDIM; d += 32) {
        float xv = xr[d];
        const float* rwr = rw + (size_t)d * NEXP;
#pragma unroll
        for (int e = 0; e < NEXP; e++) acc[e] += xv * rwr[e];
    }
#pragma unroll
    for (int e = 0; e < NEXP; e++)
#pragma unroll
        for (int off = 16; off > 0; off >>= 1)
            acc[e] += __shfl_down_sync(0xFFFFFFFFu, acc[e], off);

    if (lane == 0) {
        int e0 = 0; float l0 = acc[0];
#pragma unroll
        for (int e = 1; e < NEXP; e++)
            if (acc[e] > l0) { l0 = acc[e]; e0 = e; }
        int e1 = -1; float l1 = -3.4e38f;
#pragma unroll
        for (int e = 0; e < NEXP; e++)
            if (e != e0 && acc[e] > l1) { l1 = acc[e]; e1 = e; }
        float t  = expf(l1 - l0);   // softmax normalizer cancels in top-2 renorm
        float w0 = 1.0f / (1.0f + t);
        float w1 = t / (1.0f + t);
        g_wt[2 * warp + 0] = w0;
        g_wt[2 * warp + 1] = w1;
        int p0 = atomicAdd(&g_cnt[e0], 1);
        g_lst[e0 * T_TOK + p0] = warp * 2 + 0;
        int p1 = atomicAdd(&g_cnt[e1], 1);
        g_lst[e1 * T_TOK + p1] = warp * 2 + 1;
    }
}

// ---------------------------------------------------------------- GEMM1: h = silu(X@Wg)*(X@Wu)
__global__ __launch_bounds__(256, 1) void gemm1_kernel(
    const float* __restrict__ wg, const float* __restrict__ wu) {
    int e = blockIdx.z, mt = blockIdx.y, ft = blockIdx.x;
    int cnt = g_cnt[e];
    if (mt * BM >= cnt) return;

    extern __shared__ float dsm[];
    float* sA = dsm;                 // [S1][BM][ASTR]
    float* sG = dsm + S1 * ASZ;      // [S1][BK][BSTR]
    float* sU = sG + S1 * BSZ;       // [S1][BK][BSTR]
    __shared__ int sIdx[BM];

    int tid = threadIdx.x;
    if (tid < BM) {
        int gi = mt * BM + tid;
        sIdx[tid] = g_lst[e * T_TOK + (gi < cnt ? gi : cnt - 1)];
    }
    __syncthreads();

    const float* wgE = wg + (size_t)e * DDIM * FDIM + ft * BN;
    const float* wuE = wu + (size_t)e * DDIM * FDIM + ft * BN;

    int aRow = tid >> 3, aSeg = tid & 7;     // 32 rows x 8 segs, x4 iters -> 128 rows
    int bRow = tid >> 4, bSeg = tid & 15;    // 16 rows x 16 segs, x2 iters -> 32 rows
    const float* aP[4];
#pragma unroll
    for (int i = 0; i < 4; i++)
        aP[i] = g_xr + (size_t)(sIdx[aRow + i * 32] >> 1) * DDIM + aSeg * 4;

    int lane = tid & 31, warp = tid >> 5;
    int wm = (warp & 3) * 32, wn = (warp >> 2) * 32;
    int qr = lane >> 2, qc = lane & 3;

    float cg[2][4][4], cu[2][4][4];
#pragma unroll
    for (int i = 0; i < 2; i++)
#pragma unroll
        for (int j = 0; j < 4; j++)
#pragma unroll
            for (int k = 0; k < 4; k++) { cg[i][j][k] = 0.f; cu[i][j][k] = 0.f; }

    auto prefetch = [&](int k0, int buf) {
        float* a = sA + buf * ASZ;
#pragma unroll
        for (int i = 0; i < 4; i++)
            cpa16(a + (aRow + i * 32) * ASTR + aSeg * 4, aP[i] + k0);
        float* g = sG + buf * BSZ;
        float* u = sU + buf * BSZ;
#pragma unroll
        for (int i = 0; i < 2; i++) {
            int r = bRow + i * 16;
            cpa16(g + r * BSTR + bSeg * 4, wgE + (size_t)(k0 + r) * FDIM + bSeg * 4);
            cpa16(u + r * BSTR + bSeg * 4, wuE + (size_t)(k0 + r) * FDIM + bSeg * 4);
        }
        cpa_commit();
    };

#pragma unroll
    for (int s = 0; s < S1 - 1; s++) prefetch(s * BK, s);

    const int KT = DDIM / BK;  // 32
    for (int kt = 0; kt < KT; kt++) {
        if (kt + S1 - 1 < KT) prefetch((kt + S1 - 1) * BK, (kt + S1 - 1) % S1);
        else cpa_commit();
        cpa_wait1();
        __syncthreads();
        int buf = kt % S1;
        const float* aB = sA + buf * ASZ;
        const float* gB = sG + buf * BSZ;
        const float* uB = sU + buf * BSZ;
#pragma unroll
        for (int ks = 0; ks < 4; ks++) {
            int k = ks * 8;
            unsigned af[2][4];
#pragma unroll
            for (int mf = 0; mf < 2; mf++) {
                int r = wm + mf * 16 + qr;
                af[mf][0] = __float_as_uint(aB[r * ASTR + k + qc]);
                af[mf][1] = __float_as_uint(aB[(r + 8) * ASTR + k + qc]);
                af[mf][2] = __float_as_uint(aB[r * ASTR + k + qc + 4]);
                af[mf][3] = __float_as_uint(aB[(r + 8) * ASTR + k + qc + 4]);
            }
#pragma unroll
            for (int nf = 0; nf < 4; nf++) {
                int c = wn + nf * 8 + qr;
                unsigned bg0 = cvt_tf32(gB[(k + qc) * BSTR + c]);
                unsigned bg1 = cvt_tf32(gB[(k + qc + 4) * BSTR + c]);
                unsigned bu0 = cvt_tf32(uB[(k + qc) * BSTR + c]);
                unsigned bu1 = cvt_tf32(uB[(k + qc + 4) * BSTR + c]);
#pragma unroll
                for (int mf = 0; mf < 2; mf++) {
                    mma_tf32(cg[mf][nf][0], cg[mf][nf][1], cg[mf][nf][2], cg[mf][nf][3],
                             af[mf][0], af[mf][1], af[mf][2], af[mf][3], bg0, bg1);
                    mma_tf32(cu[mf][nf][0], cu[mf][nf][1], cu[mf][nf][2], cu[mf][nf][3],
                             af[mf][0], af[mf][1], af[mf][2], af[mf][3], bu0, bu1);
                }
            }
        }
        __syncthreads();
    }

    // epilogue: h = silu(g)*u, tf32-rounded (so gemm2 needs no A cvt), float2 stores
#pragma unroll
    for (int mf = 0; mf < 2; mf++)
#pragma unroll
        for (int half = 0; half < 2; half++) {
            int rl = wm + mf * 16 + qr + half * 8;
            int gi = mt * BM + rl;
            if (gi < cnt) {
                int a = sIdx[rl];
                float* hp = g_h + (size_t)a * FDIM + ft * BN;
#pragma unroll
                for (int nf = 0; nf < 4; nf++) {
                    float gv0 = cg[mf][nf][half * 2 + 0], gv1 = cg[mf][nf][half * 2 + 1];
                    float uv0 = cu[mf][nf][half * 2 + 0], uv1 = cu[mf][nf][half * 2 + 1];
                    float h0 = gv0 / (1.0f + __expf(-gv0)) * uv0;
                    float h1 = gv1 / (1.0f + __expf(-gv1)) * uv1;
                    int c = wn + nf * 8 + qc * 2;
                    *reinterpret_cast<float2*>(hp + c) = make_float2(
                        __uint_as_float(cvt_tf32(h0)), __uint_as_float(cvt_tf32(h1)));
                }
            }
        }
}

// ---------------------------------------------------------------- GEMM2: out += w * (h @ Wd)
__global__ __launch_bounds__(256, 1) void gemm2_kernel(
    const float* __restrict__ wd, float* __restrict__ out) {
    int e = blockIdx.z, mt = blockIdx.y, nt = blockIdx.x;
    int cnt = g_cnt[e];
    if (mt * BM >= cnt) return;

    extern __shared__ float dsm[];
    float* sA = dsm;             // [S2][BM][ASTR]
    float* sB = dsm + S2 * ASZ;  // [S2][BK][BSTR]
    __shared__ int   sIdx[BM];
    __shared__ float sW[BM];

    int tid = threadIdx.x;
    if (tid < BM) {
        int gi = mt * BM + tid;
        int a = g_lst[e * T_TOK + (gi < cnt ? gi : cnt - 1)];
        sIdx[tid] = a;
        sW[tid] = g_wt[a];
    }
    __syncthreads();

    const float* wdE = wd + (size_t)e * FDIM * DDIM + nt * BN;

    int aRow = tid >> 3, aSeg = tid & 7;
    int bRow = tid >> 4, bSeg = tid & 15;
    const float* aP[4];
#pragma unroll
    for (int i = 0; i < 4; i++)
        aP[i] = g_h + (size_t)sIdx[aRow + i * 32] * FDIM + aSeg * 4;

    int lane = tid & 31, warp = tid >> 5;
    int wm = (warp & 3) * 32, wn = (warp >> 2) * 32;
    int qr = lane >> 2, qc = lane & 3;

    float cc[2][4][4];
#pragma unroll
    for (int i = 0; i < 2; i++)
#pragma unroll
        for (int j = 0; j < 4; j++)
#pragma unroll
            for (int k = 0; k < 4; k++) cc[i][j][k] = 0.f;

    auto prefetch = [&](int k0, int buf) {
        float* a = sA + buf * ASZ;
#pragma unroll
        for (int i = 0; i < 4; i++)
            cpa16(a + (aRow + i * 32) * ASTR + aSeg * 4, aP[i] + k0);
        float* b = sB + buf * BSZ;
#pragma unroll
        for (int i = 0; i < 2; i++) {
            int r = bRow + i * 16;
            cpa16(b + r * BSTR + bSeg * 4, wdE + (size_t)(k0 + r) * DDIM + bSeg * 4);
        }
        cpa_commit();
    };

#pragma unroll
    for (int s = 0; s < S2 - 1; s++) prefetch(s * BK, s);

    const int KT = FDIM / BK;  // 64
    for (int kt = 0; kt < KT; kt++) {
        if (kt + S2 - 1 < KT) prefetch((kt + S2 - 1) * BK, (kt + S2 - 1) % S2);
        else cpa_commit();
        cpa_wait2();
        __syncthreads();
        int buf = kt % S2;
        const float* aB = sA + buf * ASZ;
        const float* bB = sB + buf * BSZ;
#pragma unroll
        for (int ks = 0; ks < 4; ks++) {
            int k = ks * 8;
            unsigned af[2][4];
#pragma unroll
            for (int mf = 0; mf < 2; mf++) {
                int r = wm + mf * 16 + qr;
                af[mf][0] = __float_as_uint(aB[r * ASTR + k + qc]);
                af[mf][1] = __float_as_uint(aB[(r + 8) * ASTR + k + qc]);
                af[mf][2] = __float_as_uint(aB[r * ASTR + k + qc + 4]);
                af[mf][3] = __float_as_uint(aB[(r + 8) * ASTR + k + qc + 4]);
            }
#pragma unroll
            for (int nf = 0; nf < 4; nf++) {
                int c = wn + nf * 8 + qr;
                unsigned b0 = cvt_tf32(bB[(k + qc) * BSTR + c]);
                unsigned b1 = cvt_tf32(bB[(k + qc + 4) * BSTR + c]);
#pragma unroll
                for (int mf = 0; mf < 2; mf++)
                    mma_tf32(cc[mf][nf][0], cc[mf][nf][1], cc[mf][nf][2], cc[mf][nf][3],
                             af[mf][0], af[mf][1], af[mf][2], af[mf][3], b0, b1);
            }
        }
        __syncthreads();
    }

    // epilogue: weighted atomic scatter (exactly 2 adds per out element -> deterministic)
#pragma unroll
    for (int mf = 0; mf < 2; mf++)
#pragma unroll
        for (int half = 0; half < 2; half++) {
            int rl = wm + mf * 16 + qr + half * 8;
            int gi = mt * BM + rl;
            if (gi < cnt) {
                int a = sIdx[rl];
                int tok = a >> 1;
                float w = sW[rl];
                float* op = out + (size_t)tok * DDIM + nt * BN;
#pragma unroll
                for (int nf = 0; nf < 4; nf++) {
                    int c = wn + nf * 8 + qc * 2;
                    atomicAdd(op + c,     cc[mf][nf][half * 2 + 0] * w);
                    atomicAdd(op + c + 1, cc[mf][nf][half * 2 + 1] * w);
                }
            }
        }
}

// ---------------------------------------------------------------- launch
extern "C" void kernel_launch(void* const* d_in, const int* in_sizes, int n_in,
                              void* d_out, int out_size) {
    const float* x  = (const float*)d_in[0];
    const float* rw = (const float*)d_in[1];
    const float* wg = (const float*)d_in[2];
    const float* wu = (const float*)d_in[3];
    const float* wd = (const float*)d_in[4];
    float* out = (float*)d_out;

    cudaFuncSetAttribute(gemm1_kernel, cudaFuncAttributeMaxDynamicSharedMemorySize, SMEM1);
    cudaFuncSetAttribute(gemm2_kernel, cudaFuncAttributeMaxDynamicSharedMemorySize, SMEM2);

    init_kernel<<<(T_TOK * DDIM + 255) / 256, 256>>>(out, x);
    router_kernel<<<(T_TOK * 32 + 255) / 256, 256>>>(x, rw);

    dim3 g1(FDIM / BN, T_TOK / BM, NEXP);  // (32, 8, 16)
    gemm1_kernel<<<g1, 256, SMEM1>>>(wg, wu);

    dim3 g2(DDIM / BN, T_TOK / BM, NEXP);  // (16, 8, 16)
    gemm2_kernel<<<g2, 256, SMEM2>>>(wd, out);
}